// round 1
// baseline (speedup 1.0000x reference)
#include <cuda_runtime.h>
#include <cuda_bf16.h>
#include <math.h>

// Problem constants
#define BB 2
#define LL 2048
#define DD 1024
#define HH 16
#define DHH 64
#define TT (BB*LL)          // 4096 tokens
#define EPS 1e-5f

// -------- scratch (device globals: allocation-free rule) --------
__device__ float g_h[TT * DD];            // LN1 output           16 MB
__device__ float g_qkv[TT * 3 * DD];      // QKV GEMM output      48 MB
__device__ float g_q[TT * DD];            // [B,H,L,DH] roped q   16 MB
__device__ float g_k[TT * DD];            // [B,H,L,DH] roped k   16 MB
__device__ float g_v[TT * DD];            // [B,H,L,DH] v         16 MB
__device__ float g_ctx[TT * DD];          // attention output     16 MB

// ---------------- block reduction helper (256 threads) ----------------
__device__ __forceinline__ void block_reduce4(float& a, float& b, float& c, float& d) {
    #pragma unroll
    for (int o = 16; o; o >>= 1) {
        a += __shfl_xor_sync(0xffffffffu, a, o);
        b += __shfl_xor_sync(0xffffffffu, b, o);
        c += __shfl_xor_sync(0xffffffffu, c, o);
        d += __shfl_xor_sync(0xffffffffu, d, o);
    }
    __shared__ float s[4][8];
    int w = threadIdx.x >> 5, lane = threadIdx.x & 31;
    if (lane == 0) { s[0][w] = a; s[1][w] = b; s[2][w] = c; s[3][w] = d; }
    __syncthreads();
    a = b = c = d = 0.f;
    #pragma unroll
    for (int i = 0; i < 8; i++) { a += s[0][i]; b += s[1][i]; c += s[2][i]; d += s[3][i]; }
    __syncthreads();
}

// ---------------- kernel 1: LN1 ----------------
// one block per token, 256 threads, 4 floats per thread
__global__ void ln1_kernel(const float* __restrict__ x,
                           const float* __restrict__ w,
                           const float* __restrict__ bia) {
    int t = blockIdx.x;
    int tid = threadIdx.x;
    const float4* xr = (const float4*)(x + (size_t)t * DD);
    float4 v = xr[tid];
    float s  = v.x + v.y + v.z + v.w;
    float ss = v.x*v.x + v.y*v.y + v.z*v.z + v.w*v.w;
    float z0 = 0.f, z1 = 0.f;
    block_reduce4(s, ss, z0, z1);
    float mu  = s * (1.0f / DD);
    float var = ss * (1.0f / DD) - mu * mu;
    float inv = rsqrtf(var + EPS);
    float4 wv = ((const float4*)w)[tid];
    float4 bv = ((const float4*)bia)[tid];
    float4 o;
    o.x = (v.x - mu) * inv * wv.x + bv.x;
    o.y = (v.y - mu) * inv * wv.y + bv.y;
    o.z = (v.z - mu) * inv * wv.z + bv.z;
    o.w = (v.w - mu) * inv * wv.w + bv.w;
    ((float4*)(g_h + (size_t)t * DD))[tid] = o;
}

// ---------------- SGEMM: C[M,N] = A[M,K] * B[N,K]^T  (both K-contiguous) ----------------
// 128x128 tile, BK=8, 256 threads, 8x8 per thread
__global__ void sgemm_tn(const float* __restrict__ A,
                         const float* __restrict__ B,
                         float* __restrict__ C,
                         int M, int N, int K) {
    __shared__ float As[8][132];
    __shared__ float Bs[8][132];
    int bm = blockIdx.y * 128;
    int bn = blockIdx.x * 128;
    int tid = threadIdx.x;
    int tx = tid & 15, ty = tid >> 4;
    int tm = ty * 8, tn = tx * 8;
    int lr = tid >> 1;            // row within tile for loads
    int lk = (tid & 1) * 4;       // k offset within BK
    const float* Ap = A + (size_t)(bm + lr) * K + lk;
    const float* Bp = B + (size_t)(bn + lr) * K + lk;

    float acc[8][8];
    #pragma unroll
    for (int i = 0; i < 8; i++)
        #pragma unroll
        for (int j = 0; j < 8; j++) acc[i][j] = 0.f;

    for (int k0 = 0; k0 < K; k0 += 8) {
        float4 av = *(const float4*)(Ap + k0);
        float4 bv = *(const float4*)(Bp + k0);
        __syncthreads();
        As[lk+0][lr] = av.x; As[lk+1][lr] = av.y; As[lk+2][lr] = av.z; As[lk+3][lr] = av.w;
        Bs[lk+0][lr] = bv.x; Bs[lk+1][lr] = bv.y; Bs[lk+2][lr] = bv.z; Bs[lk+3][lr] = bv.w;
        __syncthreads();
        #pragma unroll
        for (int kk = 0; kk < 8; kk++) {
            float a[8], b[8];
            float4 a0 = *(const float4*)&As[kk][tm];
            float4 a1 = *(const float4*)&As[kk][tm + 4];
            float4 b0 = *(const float4*)&Bs[kk][tn];
            float4 b1 = *(const float4*)&Bs[kk][tn + 4];
            a[0]=a0.x;a[1]=a0.y;a[2]=a0.z;a[3]=a0.w;a[4]=a1.x;a[5]=a1.y;a[6]=a1.z;a[7]=a1.w;
            b[0]=b0.x;b[1]=b0.y;b[2]=b0.z;b[3]=b0.w;b[4]=b1.x;b[5]=b1.y;b[6]=b1.z;b[7]=b1.w;
            #pragma unroll
            for (int i = 0; i < 8; i++)
                #pragma unroll
                for (int j = 0; j < 8; j++)
                    acc[i][j] = fmaf(a[i], b[j], acc[i][j]);
        }
    }
    #pragma unroll
    for (int i = 0; i < 8; i++) {
        float* cr = C + (size_t)(bm + tm + i) * N + bn + tn;
        *(float4*)cr       = make_float4(acc[i][0], acc[i][1], acc[i][2], acc[i][3]);
        *(float4*)(cr + 4) = make_float4(acc[i][4], acc[i][5], acc[i][6], acc[i][7]);
    }
}

// ---------------- kernel 3: QK LayerNorm + RoPE + transpose to [B,H,L,DH] ----------------
__global__ void qk_rope_kernel(const float* __restrict__ qw,
                               const float* __restrict__ kw) {
    int t = blockIdx.x;
    int b = t >> 11;          // t / 2048
    int l = t & 2047;
    int tid = threadIdx.x;
    const float4* row = (const float4*)(g_qkv + (size_t)t * 3 * DD);
    float4 q = row[tid];
    float4 k = row[256 + tid];
    float4 v = row[512 + tid];

    float qs  = q.x + q.y + q.z + q.w;
    float qss = q.x*q.x + q.y*q.y + q.z*q.z + q.w*q.w;
    float ks  = k.x + k.y + k.z + k.w;
    float kss = k.x*k.x + k.y*k.y + k.z*k.z + k.w*k.w;
    block_reduce4(qs, qss, ks, kss);
    float muq = qs * (1.0f / DD);
    float vq  = qss * (1.0f / DD) - muq * muq;
    float iq  = rsqrtf(vq + EPS);
    float muk = ks * (1.0f / DD);
    float vk  = kss * (1.0f / DD) - muk * muk;
    float ik  = rsqrtf(vk + EPS);

    __shared__ float qn[DD];
    __shared__ float kn[DD];
    float4 qwv = ((const float4*)qw)[tid];
    float4 kwv = ((const float4*)kw)[tid];
    int d0 = tid * 4;
    qn[d0+0] = (q.x - muq) * iq * qwv.x;
    qn[d0+1] = (q.y - muq) * iq * qwv.y;
    qn[d0+2] = (q.z - muq) * iq * qwv.z;
    qn[d0+3] = (q.w - muq) * iq * qwv.w;
    kn[d0+0] = (k.x - muk) * ik * kwv.x;
    kn[d0+1] = (k.y - muk) * ik * kwv.y;
    kn[d0+2] = (k.z - muk) * ik * kwv.z;
    kn[d0+3] = (k.w - muk) * ik * kwv.w;
    __syncthreads();

    int h   = d0 >> 6;
    int dh0 = d0 & 63;
    float oq[4], ok[4];
    #pragma unroll
    for (int j = 0; j < 4; j++) {
        int dh = dh0 + j;
        int fi = dh & 31;
        float invf = powf(10000.0f, -((float)(2 * fi)) / 64.0f);
        float ang  = (float)l * invf;
        float c = cosf(ang), s = sinf(ang);
        float qv = qn[d0 + j];
        float kv = kn[d0 + j];
        float qp = (dh < 32) ? -qn[d0 + j + 32] : qn[d0 + j - 32];
        float kp = (dh < 32) ? -kn[d0 + j + 32] : kn[d0 + j - 32];
        oq[j] = qv * c + qp * s;
        ok[j] = kv * c + kp * s;
    }
    size_t oidx = (((size_t)(b * HH + h) * LL + l) * DHH + dh0);
    *(float4*)(g_q + oidx) = make_float4(oq[0], oq[1], oq[2], oq[3]);
    *(float4*)(g_k + oidx) = make_float4(ok[0], ok[1], ok[2], ok[3]);
    *(float4*)(g_v + oidx) = v;  // v untouched, just transposed layout
}

// ---------------- kernel 4: flash-style masked attention ----------------
// grid (qtile=32, bh=32), 256 threads (16x16), 64x64 tiles, online softmax.
// Dynamic smem: Qs[64][65] + KPs[64][65] + Vs[64][64]
__global__ void attn_kernel(const int* __restrict__ seq_id) {
    extern __shared__ float sm[];
    float* Qs  = sm;                 // [dh][m], padded row 65
    float* KPs = sm + 64 * 65;       // K as [dh][n], later P as [n][m]
    float* Vs  = KPs + 64 * 65;      // [n][dh], row 64
    __shared__ int kseq[64];

    int qt = blockIdx.x;
    int bh = blockIdx.y;
    int b  = bh >> 4;
    int hh = bh & 15;
    int tid = threadIdx.x;
    int tx = tid & 15, ty = tid >> 4;

    const float* Qg = g_q + ((size_t)bh * LL + qt * 64) * DHH;
    #pragma unroll
    for (int i = 0; i < 4; i++) {
        int idx = tid + i * 256;
        int m = idx >> 4;
        int d4 = (idx & 15) * 4;
        float4 qv = *(const float4*)(Qg + m * DHH + d4);
        Qs[(d4+0)*65 + m] = qv.x;
        Qs[(d4+1)*65 + m] = qv.y;
        Qs[(d4+2)*65 + m] = qv.z;
        Qs[(d4+3)*65 + m] = qv.w;
    }
    int qseq[4];
    #pragma unroll
    for (int i = 0; i < 4; i++)
        qseq[i] = seq_id[b * LL + qt * 64 + ty * 4 + i];

    float m_i[4], l_i[4], O[4][4];
    #pragma unroll
    for (int i = 0; i < 4; i++) {
        m_i[i] = -1e30f; l_i[i] = 0.f;
        #pragma unroll
        for (int j = 0; j < 4; j++) O[i][j] = 0.f;
    }

    for (int kt = 0; kt < LL / 64; kt++) {
        __syncthreads();
        const float* Kg = g_k + ((size_t)bh * LL + kt * 64) * DHH;
        const float* Vg = g_v + ((size_t)bh * LL + kt * 64) * DHH;
        #pragma unroll
        for (int i = 0; i < 4; i++) {
            int idx = tid + i * 256;
            int n = idx >> 4;
            int d4 = (idx & 15) * 4;
            float4 kv = *(const float4*)(Kg + n * DHH + d4);
            KPs[(d4+0)*65 + n] = kv.x;
            KPs[(d4+1)*65 + n] = kv.y;
            KPs[(d4+2)*65 + n] = kv.z;
            KPs[(d4+3)*65 + n] = kv.w;
            float4 vv = *(const float4*)(Vg + n * DHH + d4);
            *(float4*)&Vs[n * 64 + d4] = vv;
        }
        if (tid < 64) kseq[tid] = seq_id[b * LL + kt * 64 + tid];
        __syncthreads();

        // S = Q K^T (4x4 per thread)
        float S[4][4];
        #pragma unroll
        for (int i = 0; i < 4; i++)
            #pragma unroll
            for (int j = 0; j < 4; j++) S[i][j] = 0.f;
        for (int kk = 0; kk < 64; kk++) {
            float a0 = Qs[kk*65 + ty*4 + 0];
            float a1 = Qs[kk*65 + ty*4 + 1];
            float a2 = Qs[kk*65 + ty*4 + 2];
            float a3 = Qs[kk*65 + ty*4 + 3];
            float b0 = KPs[kk*65 + tx*4 + 0];
            float b1 = KPs[kk*65 + tx*4 + 1];
            float b2 = KPs[kk*65 + tx*4 + 2];
            float b3 = KPs[kk*65 + tx*4 + 3];
            S[0][0] = fmaf(a0,b0,S[0][0]); S[0][1] = fmaf(a0,b1,S[0][1]);
            S[0][2] = fmaf(a0,b2,S[0][2]); S[0][3] = fmaf(a0,b3,S[0][3]);
            S[1][0] = fmaf(a1,b0,S[1][0]); S[1][1] = fmaf(a1,b1,S[1][1]);
            S[1][2] = fmaf(a1,b2,S[1][2]); S[1][3] = fmaf(a1,b3,S[1][3]);
            S[2][0] = fmaf(a2,b0,S[2][0]); S[2][1] = fmaf(a2,b1,S[2][1]);
            S[2][2] = fmaf(a2,b2,S[2][2]); S[2][3] = fmaf(a2,b3,S[2][3]);
            S[3][0] = fmaf(a3,b0,S[3][0]); S[3][1] = fmaf(a3,b1,S[3][1]);
            S[3][2] = fmaf(a3,b2,S[3][2]); S[3][3] = fmaf(a3,b3,S[3][3]);
        }

        // mask + scale
        int kse[4];
        #pragma unroll
        for (int j = 0; j < 4; j++) kse[j] = kseq[tx * 4 + j];
        #pragma unroll
        for (int i = 0; i < 4; i++)
            #pragma unroll
            for (int j = 0; j < 4; j++)
                S[i][j] = (qseq[i] == kse[j]) ? S[i][j] * 0.125f : -1e30f;

        // online softmax update
        float scl[4];
        #pragma unroll
        for (int i = 0; i < 4; i++) {
            float rmax = fmaxf(fmaxf(S[i][0], S[i][1]), fmaxf(S[i][2], S[i][3]));
            #pragma unroll
            for (int o = 8; o; o >>= 1)
                rmax = fmaxf(rmax, __shfl_xor_sync(0xffffffffu, rmax, o));
            float mn = fmaxf(m_i[i], rmax);
            scl[i] = expf(m_i[i] - mn);
            m_i[i] = mn;
            float rsum = 0.f;
            #pragma unroll
            for (int j = 0; j < 4; j++) {
                float p = expf(S[i][j] - mn);
                S[i][j] = p;
                rsum += p;
            }
            #pragma unroll
            for (int o = 8; o; o >>= 1)
                rsum += __shfl_xor_sync(0xffffffffu, rsum, o);
            l_i[i] = l_i[i] * scl[i] + rsum;
            #pragma unroll
            for (int j = 0; j < 4; j++) O[i][j] *= scl[i];
        }

        __syncthreads();   // done reading K from KPs
        // write P transposed: KPs[n][m]
        #pragma unroll
        for (int i = 0; i < 4; i++)
            #pragma unroll
            for (int j = 0; j < 4; j++)
                KPs[(tx*4 + j)*65 + ty*4 + i] = S[i][j];
        __syncthreads();

        // O += P V
        for (int nn = 0; nn < 64; nn++) {
            float a0 = KPs[nn*65 + ty*4 + 0];
            float a1 = KPs[nn*65 + ty*4 + 1];
            float a2 = KPs[nn*65 + ty*4 + 2];
            float a3 = KPs[nn*65 + ty*4 + 3];
            float4 bv = *(const float4*)&Vs[nn*64 + tx*4];
            O[0][0] = fmaf(a0,bv.x,O[0][0]); O[0][1] = fmaf(a0,bv.y,O[0][1]);
            O[0][2] = fmaf(a0,bv.z,O[0][2]); O[0][3] = fmaf(a0,bv.w,O[0][3]);
            O[1][0] = fmaf(a1,bv.x,O[1][0]); O[1][1] = fmaf(a1,bv.y,O[1][1]);
            O[1][2] = fmaf(a1,bv.z,O[1][2]); O[1][3] = fmaf(a1,bv.w,O[1][3]);
            O[2][0] = fmaf(a2,bv.x,O[2][0]); O[2][1] = fmaf(a2,bv.y,O[2][1]);
            O[2][2] = fmaf(a2,bv.z,O[2][2]); O[2][3] = fmaf(a2,bv.w,O[2][3]);
            O[3][0] = fmaf(a3,bv.x,O[3][0]); O[3][1] = fmaf(a3,bv.y,O[3][1]);
            O[3][2] = fmaf(a3,bv.z,O[3][2]); O[3][3] = fmaf(a3,bv.w,O[3][3]);
        }
    }

    // finalize: ctx[t][hh*64 + dh]
    #pragma unroll
    for (int i = 0; i < 4; i++) {
        float inv = 1.0f / l_i[i];
        int t = b * LL + qt * 64 + ty * 4 + i;
        float4 o = make_float4(O[i][0]*inv, O[i][1]*inv, O[i][2]*inv, O[i][3]*inv);
        *(float4*)(g_ctx + (size_t)t * DD + hh * DHH + tx * 4) = o;
    }
}

// ---------------- launch ----------------
extern "C" void kernel_launch(void* const* d_in, const int* in_sizes, int n_in,
                              void* d_out, int out_size) {
    const float* x     = (const float*)d_in[0];
    const int*   seq   = (const int*)  d_in[1];
    const float* ln1w  = (const float*)d_in[2];
    const float* ln1b  = (const float*)d_in[3];
    const float* wqkv  = (const float*)d_in[4];
    const float* qlnw  = (const float*)d_in[5];
    const float* klnw  = (const float*)d_in[6];
    const float* outw  = (const float*)d_in[7];
    float* out = (float*)d_out;

    void *ph, *pqkv, *pctx;
    cudaGetSymbolAddress(&ph, g_h);
    cudaGetSymbolAddress(&pqkv, g_qkv);
    cudaGetSymbolAddress(&pctx, g_ctx);

    // 1) LN1
    ln1_kernel<<<TT, 256>>>(x, ln1w, ln1b);

    // 2) QKV GEMM: [4096,3072] = h[4096,1024] x wqkv[3072,1024]^T
    sgemm_tn<<<dim3(3 * DD / 128, TT / 128), 256>>>((const float*)ph, wqkv, (float*)pqkv,
                                                    TT, 3 * DD, DD);

    // 3) QK LN + RoPE + transpose
    qk_rope_kernel<<<TT, 256>>>(qlnw, klnw);

    // 4) attention
    const int attn_smem = (64 * 65 + 64 * 65 + 64 * 64) * (int)sizeof(float); // 49664
    static bool attr_set_done = false; // idempotent attribute set (not a work guard)
    cudaFuncSetAttribute(attn_kernel, cudaFuncAttributeMaxDynamicSharedMemorySize, attn_smem);
    (void)attr_set_done;
    attn_kernel<<<dim3(LL / 64, BB * HH), 256, attn_smem>>>(seq);

    // 5) output projection: [4096,1024] = ctx x out_w^T
    sgemm_tn<<<dim3(DD / 128, TT / 128), 256>>>((const float*)pctx, outw, out,
                                                TT, DD, DD);
}

// round 3
// speedup vs baseline: 1.4962x; 1.4962x over previous
#include <cuda_runtime.h>
#include <cuda_bf16.h>
#include <cstdint>
#include <math.h>

// Problem constants
#define BB 2
#define LL 2048
#define DD 1024
#define HH 16
#define DHH 64
#define TT (BB*LL)          // 4096 tokens
#define EPS 1e-5f

// -------- scratch (device globals: allocation-free rule) --------
__device__ float g_h[TT * DD];            // LN1 output
__device__ float g_qkv[TT * 3 * DD];      // QKV GEMM output
__device__ float g_q[TT * DD];            // [B,H,L,DH] roped q
__device__ float g_k[TT * DD];            // [B,H,L,DH] roped k
__device__ float g_v[TT * DD];            // [B,H,L,DH] v
__device__ float g_ctx[TT * DD];          // attention output

__device__ __forceinline__ uint32_t f2tf32(float f) {
    uint32_t r; asm("cvt.rna.tf32.f32 %0, %1;" : "=r"(r) : "f"(f)); return r;
}

__device__ __forceinline__ void mma16n8k8(float* d, const uint32_t* a,
                                          uint32_t b0, uint32_t b1) {
    asm volatile(
        "mma.sync.aligned.m16n8k8.row.col.f32.tf32.tf32.f32 "
        "{%0,%1,%2,%3}, {%4,%5,%6,%7}, {%8,%9}, {%0,%1,%2,%3};"
        : "+f"(d[0]), "+f"(d[1]), "+f"(d[2]), "+f"(d[3])
        : "r"(a[0]), "r"(a[1]), "r"(a[2]), "r"(a[3]), "r"(b0), "r"(b1));
}

// ===================== tf32 mma.sync GEMM =====================
// C[M,N] = A[M,1024] * B[N,1024]^T. Tile 128x128, BK=32, 8 warps (32x64 each).
#define GK 1024
#define BKc 32
#define NCHUNK (GK / BKc)    // 32
#define PADs 36
#define BUF_F (128 * PADs)   // floats per (matrix, buffer)
#define GEMM_SMEM (4 * BUF_F * 4)   // 2 bufs x (A+B) = 73728 B

__global__ __launch_bounds__(256)
void gemm_mma_tf32(const float* __restrict__ A, const float* __restrict__ B,
                   float* __restrict__ C, int N) {
    extern __shared__ float sm[];
    float* As = sm;                 // [2][128][PADs]
    float* Bs = sm + 2 * BUF_F;     // [2][128][PADs]

    const int tid = threadIdx.x;
    const int wid = tid >> 5, lane = tid & 31;
    const int grp = lane >> 2, qd = lane & 3;
    const int wm = wid >> 1, wn = wid & 1;   // 4 m-warps x 2 n-warps
    const int m0 = blockIdx.y * 128;
    const int n0 = blockIdx.x * 128;

    const int lrow = tid >> 3;       // 0..31 used as u>>3 base pattern
    (void)lrow;

    float acc[2][8][4];
    #pragma unroll
    for (int i = 0; i < 2; i++)
        #pragma unroll
        for (int j = 0; j < 8; j++)
            #pragma unroll
            for (int q = 0; q < 4; q++) acc[i][j][q] = 0.f;

    float4 pa[4], pb[4];
    // load chunk 0
    #pragma unroll
    for (int i = 0; i < 4; i++) {
        int u = tid + i * 256;
        int r = u >> 3, c4 = u & 7;
        pa[i] = *(const float4*)(A + (size_t)(m0 + r) * GK + c4 * 4);
        pb[i] = *(const float4*)(B + (size_t)(n0 + r) * GK + c4 * 4);
    }
    #pragma unroll
    for (int i = 0; i < 4; i++) {
        int u = tid + i * 256;
        int r = u >> 3, c4 = u & 7;
        float* pA = As + r * PADs + c4 * 4;
        pA[0] = __uint_as_float(f2tf32(pa[i].x));
        pA[1] = __uint_as_float(f2tf32(pa[i].y));
        pA[2] = __uint_as_float(f2tf32(pa[i].z));
        pA[3] = __uint_as_float(f2tf32(pa[i].w));
        float* pB = Bs + r * PADs + c4 * 4;
        pB[0] = __uint_as_float(f2tf32(pb[i].x));
        pB[1] = __uint_as_float(f2tf32(pb[i].y));
        pB[2] = __uint_as_float(f2tf32(pb[i].z));
        pB[3] = __uint_as_float(f2tf32(pb[i].w));
    }
    __syncthreads();

    for (int ic = 0; ic < NCHUNK; ic++) {
        // prefetch next chunk into registers
        if (ic + 1 < NCHUNK) {
            const float* An = A + (ic + 1) * BKc;
            const float* Bn = B + (ic + 1) * BKc;
            #pragma unroll
            for (int i = 0; i < 4; i++) {
                int u = tid + i * 256;
                int r = u >> 3, c4 = u & 7;
                pa[i] = *(const float4*)(An + (size_t)(m0 + r) * GK + c4 * 4);
                pb[i] = *(const float4*)(Bn + (size_t)(n0 + r) * GK + c4 * 4);
            }
        }

        const float* Ab = As + (ic & 1) * BUF_F;
        const float* Bb = Bs + (ic & 1) * BUF_F;
        #pragma unroll
        for (int ks = 0; ks < 4; ks++) {
            int kb = ks * 8;
            uint32_t af[2][4];
            #pragma unroll
            for (int mt = 0; mt < 2; mt++) {
                int r = wm * 32 + mt * 16 + grp;
                af[mt][0] = __float_as_uint(Ab[r * PADs + kb + qd]);
                af[mt][1] = __float_as_uint(Ab[(r + 8) * PADs + kb + qd]);
                af[mt][2] = __float_as_uint(Ab[r * PADs + kb + qd + 4]);
                af[mt][3] = __float_as_uint(Ab[(r + 8) * PADs + kb + qd + 4]);
            }
            #pragma unroll
            for (int nt = 0; nt < 8; nt++) {
                int c = wn * 64 + nt * 8 + grp;
                uint32_t b0 = __float_as_uint(Bb[c * PADs + kb + qd]);
                uint32_t b1 = __float_as_uint(Bb[c * PADs + kb + qd + 4]);
                mma16n8k8(acc[0][nt], af[0], b0, b1);
                mma16n8k8(acc[1][nt], af[1], b0, b1);
            }
        }

        if (ic + 1 < NCHUNK) {
            float* Ad = As + ((ic + 1) & 1) * BUF_F;
            float* Bd = Bs + ((ic + 1) & 1) * BUF_F;
            #pragma unroll
            for (int i = 0; i < 4; i++) {
                int u = tid + i * 256;
                int r = u >> 3, c4 = u & 7;
                float* pA = Ad + r * PADs + c4 * 4;
                pA[0] = __uint_as_float(f2tf32(pa[i].x));
                pA[1] = __uint_as_float(f2tf32(pa[i].y));
                pA[2] = __uint_as_float(f2tf32(pa[i].z));
                pA[3] = __uint_as_float(f2tf32(pa[i].w));
                float* pB = Bd + r * PADs + c4 * 4;
                pB[0] = __uint_as_float(f2tf32(pb[i].x));
                pB[1] = __uint_as_float(f2tf32(pb[i].y));
                pB[2] = __uint_as_float(f2tf32(pb[i].z));
                pB[3] = __uint_as_float(f2tf32(pb[i].w));
            }
            __syncthreads();
        }
    }

    // epilogue: direct float2 stores
    #pragma unroll
    for (int mt = 0; mt < 2; mt++) {
        #pragma unroll
        for (int nt = 0; nt < 8; nt++) {
            int r = m0 + wm * 32 + mt * 16 + grp;
            int c = n0 + wn * 64 + nt * 8 + qd * 2;
            *(float2*)(C + (size_t)r * N + c) =
                make_float2(acc[mt][nt][0], acc[mt][nt][1]);
            *(float2*)(C + (size_t)(r + 8) * N + c) =
                make_float2(acc[mt][nt][2], acc[mt][nt][3]);
        }
    }
}

// ---------------- block reduction helper (256 threads) ----------------
__device__ __forceinline__ void block_reduce4(float& a, float& b, float& c, float& d) {
    #pragma unroll
    for (int o = 16; o; o >>= 1) {
        a += __shfl_xor_sync(0xffffffffu, a, o);
        b += __shfl_xor_sync(0xffffffffu, b, o);
        c += __shfl_xor_sync(0xffffffffu, c, o);
        d += __shfl_xor_sync(0xffffffffu, d, o);
    }
    __shared__ float s[4][8];
    int w = threadIdx.x >> 5, lane = threadIdx.x & 31;
    if (lane == 0) { s[0][w] = a; s[1][w] = b; s[2][w] = c; s[3][w] = d; }
    __syncthreads();
    a = b = c = d = 0.f;
    #pragma unroll
    for (int i = 0; i < 8; i++) { a += s[0][i]; b += s[1][i]; c += s[2][i]; d += s[3][i]; }
    __syncthreads();
}

// ---------------- kernel 1: LN1 ----------------
__global__ void ln1_kernel(const float* __restrict__ x,
                           const float* __restrict__ w,
                           const float* __restrict__ bia) {
    int t = blockIdx.x;
    int tid = threadIdx.x;
    const float4* xr = (const float4*)(x + (size_t)t * DD);
    float4 v = xr[tid];
    float s  = v.x + v.y + v.z + v.w;
    float ss = v.x*v.x + v.y*v.y + v.z*v.z + v.w*v.w;
    float z0 = 0.f, z1 = 0.f;
    block_reduce4(s, ss, z0, z1);
    float mu  = s * (1.0f / DD);
    float var = ss * (1.0f / DD) - mu * mu;
    float inv = rsqrtf(var + EPS);
    float4 wv = ((const float4*)w)[tid];
    float4 bv = ((const float4*)bia)[tid];
    float4 o;
    o.x = (v.x - mu) * inv * wv.x + bv.x;
    o.y = (v.y - mu) * inv * wv.y + bv.y;
    o.z = (v.z - mu) * inv * wv.z + bv.z;
    o.w = (v.w - mu) * inv * wv.w + bv.w;
    ((float4*)(g_h + (size_t)t * DD))[tid] = o;
}

// ---------------- kernel 3: QK LayerNorm + RoPE + transpose ----------------
__global__ void qk_rope_kernel(const float* __restrict__ qw,
                               const float* __restrict__ kw) {
    int t = blockIdx.x;
    int b = t >> 11;
    int l = t & 2047;
    int tid = threadIdx.x;
    const float4* row = (const float4*)(g_qkv + (size_t)t * 3 * DD);
    float4 q = row[tid];
    float4 k = row[256 + tid];
    float4 v = row[512 + tid];

    float qs  = q.x + q.y + q.z + q.w;
    float qss = q.x*q.x + q.y*q.y + q.z*q.z + q.w*q.w;
    float ks  = k.x + k.y + k.z + k.w;
    float kss = k.x*k.x + k.y*k.y + k.z*k.z + k.w*k.w;
    block_reduce4(qs, qss, ks, kss);
    float muq = qs * (1.0f / DD);
    float vq  = qss * (1.0f / DD) - muq * muq;
    float iq  = rsqrtf(vq + EPS);
    float muk = ks * (1.0f / DD);
    float vk  = kss * (1.0f / DD) - muk * muk;
    float ik  = rsqrtf(vk + EPS);

    __shared__ float qn[DD];
    __shared__ float kn[DD];
    float4 qwv = ((const float4*)qw)[tid];
    float4 kwv = ((const float4*)kw)[tid];
    int d0 = tid * 4;
    qn[d0+0] = (q.x - muq) * iq * qwv.x;
    qn[d0+1] = (q.y - muq) * iq * qwv.y;
    qn[d0+2] = (q.z - muq) * iq * qwv.z;
    qn[d0+3] = (q.w - muq) * iq * qwv.w;
    kn[d0+0] = (k.x - muk) * ik * kwv.x;
    kn[d0+1] = (k.y - muk) * ik * kwv.y;
    kn[d0+2] = (k.z - muk) * ik * kwv.z;
    kn[d0+3] = (k.w - muk) * ik * kwv.w;
    __syncthreads();

    int h   = d0 >> 6;
    int dh0 = d0 & 63;
    float oq[4], ok[4];
    #pragma unroll
    for (int j = 0; j < 4; j++) {
        int dh = dh0 + j;
        int fi = dh & 31;
        float invf = powf(10000.0f, -((float)(2 * fi)) / 64.0f);
        float ang  = (float)l * invf;
        float c = cosf(ang), s = sinf(ang);
        float qv = qn[d0 + j];
        float kv = kn[d0 + j];
        float qp = (dh < 32) ? -qn[d0 + j + 32] : qn[d0 + j - 32];
        float kp = (dh < 32) ? -kn[d0 + j + 32] : kn[d0 + j - 32];
        oq[j] = qv * c + qp * s;
        ok[j] = kv * c + kp * s;
    }
    size_t oidx = (((size_t)(b * HH + h) * LL + l) * DHH + dh0);
    *(float4*)(g_q + oidx) = make_float4(oq[0], oq[1], oq[2], oq[3]);
    *(float4*)(g_k + oidx) = make_float4(ok[0], ok[1], ok[2], ok[3]);
    *(float4*)(g_v + oidx) = v;
}

// ---------------- kernel 4: flash-style masked attention ----------------
__global__ void attn_kernel(const int* __restrict__ seq_id) {
    extern __shared__ float smf[];
    float* Qs  = smf;
    float* KPs = smf + 64 * 65;
    float* Vs  = KPs + 64 * 65;
    __shared__ int kseq[64];

    int qt = blockIdx.x;
    int bh = blockIdx.y;
    int b  = bh >> 4;
    int hh = bh & 15;
    int tid = threadIdx.x;
    int tx = tid & 15, ty = tid >> 4;

    const float* Qg = g_q + ((size_t)bh * LL + qt * 64) * DHH;
    #pragma unroll
    for (int i = 0; i < 4; i++) {
        int idx = tid + i * 256;
        int m = idx >> 4;
        int d4 = (idx & 15) * 4;
        float4 qv = *(const float4*)(Qg + m * DHH + d4);
        Qs[(d4+0)*65 + m] = qv.x;
        Qs[(d4+1)*65 + m] = qv.y;
        Qs[(d4+2)*65 + m] = qv.z;
        Qs[(d4+3)*65 + m] = qv.w;
    }
    int qseq[4];
    #pragma unroll
    for (int i = 0; i < 4; i++)
        qseq[i] = seq_id[b * LL + qt * 64 + ty * 4 + i];

    float m_i[4], l_i[4], O[4][4];
    #pragma unroll
    for (int i = 0; i < 4; i++) {
        m_i[i] = -1e30f; l_i[i] = 0.f;
        #pragma unroll
        for (int j = 0; j < 4; j++) O[i][j] = 0.f;
    }

    for (int kt = 0; kt < LL / 64; kt++) {
        __syncthreads();
        const float* Kg = g_k + ((size_t)bh * LL + kt * 64) * DHH;
        const float* Vg = g_v + ((size_t)bh * LL + kt * 64) * DHH;
        #pragma unroll
        for (int i = 0; i < 4; i++) {
            int idx = tid + i * 256;
            int n = idx >> 4;
            int d4 = (idx & 15) * 4;
            float4 kv = *(const float4*)(Kg + n * DHH + d4);
            KPs[(d4+0)*65 + n] = kv.x;
            KPs[(d4+1)*65 + n] = kv.y;
            KPs[(d4+2)*65 + n] = kv.z;
            KPs[(d4+3)*65 + n] = kv.w;
            float4 vv = *(const float4*)(Vg + n * DHH + d4);
            *(float4*)&Vs[n * 64 + d4] = vv;
        }
        if (tid < 64) kseq[tid] = seq_id[b * LL + kt * 64 + tid];
        __syncthreads();

        float S[4][4];
        #pragma unroll
        for (int i = 0; i < 4; i++)
            #pragma unroll
            for (int j = 0; j < 4; j++) S[i][j] = 0.f;
        for (int kk = 0; kk < 64; kk++) {
            float a0 = Qs[kk*65 + ty*4 + 0];
            float a1 = Qs[kk*65 + ty*4 + 1];
            float a2 = Qs[kk*65 + ty*4 + 2];
            float a3 = Qs[kk*65 + ty*4 + 3];
            float b0 = KPs[kk*65 + tx*4 + 0];
            float b1 = KPs[kk*65 + tx*4 + 1];
            float b2 = KPs[kk*65 + tx*4 + 2];
            float b3 = KPs[kk*65 + tx*4 + 3];
            S[0][0] = fmaf(a0,b0,S[0][0]); S[0][1] = fmaf(a0,b1,S[0][1]);
            S[0][2] = fmaf(a0,b2,S[0][2]); S[0][3] = fmaf(a0,b3,S[0][3]);
            S[1][0] = fmaf(a1,b0,S[1][0]); S[1][1] = fmaf(a1,b1,S[1][1]);
            S[1][2] = fmaf(a1,b2,S[1][2]); S[1][3] = fmaf(a1,b3,S[1][3]);
            S[2][0] = fmaf(a2,b0,S[2][0]); S[2][1] = fmaf(a2,b1,S[2][1]);
            S[2][2] = fmaf(a2,b2,S[2][2]); S[2][3] = fmaf(a2,b3,S[2][3]);
            S[3][0] = fmaf(a3,b0,S[3][0]); S[3][1] = fmaf(a3,b1,S[3][1]);
            S[3][2] = fmaf(a3,b2,S[3][2]); S[3][3] = fmaf(a3,b3,S[3][3]);
        }

        int kse[4];
        #pragma unroll
        for (int j = 0; j < 4; j++) kse[j] = kseq[tx * 4 + j];
        #pragma unroll
        for (int i = 0; i < 4; i++)
            #pragma unroll
            for (int j = 0; j < 4; j++)
                S[i][j] = (qseq[i] == kse[j]) ? S[i][j] * 0.125f : -1e30f;

        float scl[4];
        #pragma unroll
        for (int i = 0; i < 4; i++) {
            float rmax = fmaxf(fmaxf(S[i][0], S[i][1]), fmaxf(S[i][2], S[i][3]));
            #pragma unroll
            for (int o = 8; o; o >>= 1)
                rmax = fmaxf(rmax, __shfl_xor_sync(0xffffffffu, rmax, o));
            float mn = fmaxf(m_i[i], rmax);
            scl[i] = expf(m_i[i] - mn);
            m_i[i] = mn;
            float rsum = 0.f;
            #pragma unroll
            for (int j = 0; j < 4; j++) {
                float p = expf(S[i][j] - mn);
                S[i][j] = p;
                rsum += p;
            }
            #pragma unroll
            for (int o = 8; o; o >>= 1)
                rsum += __shfl_xor_sync(0xffffffffu, rsum, o);
            l_i[i] = l_i[i] * scl[i] + rsum;
            #pragma unroll
            for (int j = 0; j < 4; j++) O[i][j] *= scl[i];
        }

        __syncthreads();
        #pragma unroll
        for (int i = 0; i < 4; i++)
            #pragma unroll
            for (int j = 0; j < 4; j++)
                KPs[(tx*4 + j)*65 + ty*4 + i] = S[i][j];
        __syncthreads();

        for (int nn = 0; nn < 64; nn++) {
            float a0 = KPs[nn*65 + ty*4 + 0];
            float a1 = KPs[nn*65 + ty*4 + 1];
            float a2 = KPs[nn*65 + ty*4 + 2];
            float a3 = KPs[nn*65 + ty*4 + 3];
            float4 bv = *(const float4*)&Vs[nn*64 + tx*4];
            O[0][0] = fmaf(a0,bv.x,O[0][0]); O[0][1] = fmaf(a0,bv.y,O[0][1]);
            O[0][2] = fmaf(a0,bv.z,O[0][2]); O[0][3] = fmaf(a0,bv.w,O[0][3]);
            O[1][0] = fmaf(a1,bv.x,O[1][0]); O[1][1] = fmaf(a1,bv.y,O[1][1]);
            O[1][2] = fmaf(a1,bv.z,O[1][2]); O[1][3] = fmaf(a1,bv.w,O[1][3]);
            O[2][0] = fmaf(a2,bv.x,O[2][0]); O[2][1] = fmaf(a2,bv.y,O[2][1]);
            O[2][2] = fmaf(a2,bv.z,O[2][2]); O[2][3] = fmaf(a2,bv.w,O[2][3]);
            O[3][0] = fmaf(a3,bv.x,O[3][0]); O[3][1] = fmaf(a3,bv.y,O[3][1]);
            O[3][2] = fmaf(a3,bv.z,O[3][2]); O[3][3] = fmaf(a3,bv.w,O[3][3]);
        }
    }

    #pragma unroll
    for (int i = 0; i < 4; i++) {
        float inv = 1.0f / l_i[i];
        int t = b * LL + qt * 64 + ty * 4 + i;
        float4 o = make_float4(O[i][0]*inv, O[i][1]*inv, O[i][2]*inv, O[i][3]*inv);
        *(float4*)(g_ctx + (size_t)t * DD + hh * DHH + tx * 4) = o;
    }
}

// ---------------- launch ----------------
extern "C" void kernel_launch(void* const* d_in, const int* in_sizes, int n_in,
                              void* d_out, int out_size) {
    const float* x     = (const float*)d_in[0];
    const int*   seq   = (const int*)  d_in[1];
    const float* ln1w  = (const float*)d_in[2];
    const float* ln1b  = (const float*)d_in[3];
    const float* wqkv  = (const float*)d_in[4];
    const float* qlnw  = (const float*)d_in[5];
    const float* klnw  = (const float*)d_in[6];
    const float* outw  = (const float*)d_in[7];
    float* out = (float*)d_out;

    void *ph, *pqkv, *pctx;
    cudaGetSymbolAddress(&ph, g_h);
    cudaGetSymbolAddress(&pqkv, g_qkv);
    cudaGetSymbolAddress(&pctx, g_ctx);

    cudaFuncSetAttribute(gemm_mma_tf32, cudaFuncAttributeMaxDynamicSharedMemorySize, GEMM_SMEM);

    // 1) LN1
    ln1_kernel<<<TT, 256>>>(x, ln1w, ln1b);

    // 2) QKV GEMM: [4096,3072] = h x wqkv^T  (tf32 mma.sync)
    gemm_mma_tf32<<<dim3(3 * DD / 128, TT / 128), 256, GEMM_SMEM>>>(
        (const float*)ph, wqkv, (float*)pqkv, 3 * DD);

    // 3) QK LN + RoPE + transpose
    qk_rope_kernel<<<TT, 256>>>(qlnw, klnw);

    // 4) attention
    const int attn_smem = (64 * 65 + 64 * 65 + 64 * 64) * (int)sizeof(float);
    cudaFuncSetAttribute(attn_kernel, cudaFuncAttributeMaxDynamicSharedMemorySize, attn_smem);
    attn_kernel<<<dim3(LL / 64, BB * HH), 256, attn_smem>>>(seq);

    // 5) output projection: [4096,1024] = ctx x out_w^T  (tf32 mma.sync)
    gemm_mma_tf32<<<dim3(DD / 128, TT / 128), 256, GEMM_SMEM>>>(
        (const float*)pctx, outw, out, DD);
}

// round 4
// speedup vs baseline: 3.7050x; 2.4762x over previous
#include <cuda_runtime.h>
#include <cuda_bf16.h>
#include <cstdint>
#include <math.h>

// Problem constants
#define BB 2
#define LL 2048
#define DD 1024
#define HH 16
#define DHH 64
#define TT (BB*LL)          // 4096 tokens
#define EPS 1e-5f

// -------- scratch (device globals: allocation-free rule) --------
__device__ float g_h[TT * DD];            // LN1 output
__device__ float g_qkv[TT * 3 * DD];      // QKV GEMM output
__device__ float g_q[TT * DD];            // [B,H,L,DH] roped q
__device__ float g_k[TT * DD];            // [B,H,L,DH] roped k
__device__ float g_v[TT * DD];            // [B,H,L,DH] v
__device__ float g_ctx[TT * DD];          // attention output

__device__ __forceinline__ uint32_t f2tf32(float f) {
    uint32_t r; asm("cvt.rna.tf32.f32 %0, %1;" : "=r"(r) : "f"(f)); return r;
}

__device__ __forceinline__ void mma16n8k8(float* d, const uint32_t* a,
                                          uint32_t b0, uint32_t b1) {
    asm volatile(
        "mma.sync.aligned.m16n8k8.row.col.f32.tf32.tf32.f32 "
        "{%0,%1,%2,%3}, {%4,%5,%6,%7}, {%8,%9}, {%0,%1,%2,%3};"
        : "+f"(d[0]), "+f"(d[1]), "+f"(d[2]), "+f"(d[3])
        : "r"(a[0]), "r"(a[1]), "r"(a[2]), "r"(a[3]), "r"(b0), "r"(b1));
}

// ===================== tf32 mma.sync GEMM =====================
// C[M,N] = A[M,1024] * B[N,1024]^T. Tile 128x128, BK=32, 8 warps (32x64 each).
#define GK 1024
#define BKc 32
#define NCHUNK (GK / BKc)    // 32
#define PADs 36
#define BUF_F (128 * PADs)   // floats per (matrix, buffer)
#define GEMM_SMEM (4 * BUF_F * 4)   // 2 bufs x (A+B) = 73728 B

__global__ __launch_bounds__(256)
void gemm_mma_tf32(const float* __restrict__ A, const float* __restrict__ B,
                   float* __restrict__ C, int N) {
    extern __shared__ float sm[];
    float* As = sm;                 // [2][128][PADs]
    float* Bs = sm + 2 * BUF_F;     // [2][128][PADs]

    const int tid = threadIdx.x;
    const int wid = tid >> 5, lane = tid & 31;
    const int grp = lane >> 2, qd = lane & 3;
    const int wm = wid >> 1, wn = wid & 1;   // 4 m-warps x 2 n-warps
    const int m0 = blockIdx.y * 128;
    const int n0 = blockIdx.x * 128;

    float acc[2][8][4];
    #pragma unroll
    for (int i = 0; i < 2; i++)
        #pragma unroll
        for (int j = 0; j < 8; j++)
            #pragma unroll
            for (int q = 0; q < 4; q++) acc[i][j][q] = 0.f;

    float4 pa[4], pb[4];
    // load chunk 0
    #pragma unroll
    for (int i = 0; i < 4; i++) {
        int u = tid + i * 256;
        int r = u >> 3, c4 = u & 7;
        pa[i] = *(const float4*)(A + (size_t)(m0 + r) * GK + c4 * 4);
        pb[i] = *(const float4*)(B + (size_t)(n0 + r) * GK + c4 * 4);
    }
    #pragma unroll
    for (int i = 0; i < 4; i++) {
        int u = tid + i * 256;
        int r = u >> 3, c4 = u & 7;
        float* pA = As + r * PADs + c4 * 4;
        pA[0] = __uint_as_float(f2tf32(pa[i].x));
        pA[1] = __uint_as_float(f2tf32(pa[i].y));
        pA[2] = __uint_as_float(f2tf32(pa[i].z));
        pA[3] = __uint_as_float(f2tf32(pa[i].w));
        float* pB = Bs + r * PADs + c4 * 4;
        pB[0] = __uint_as_float(f2tf32(pb[i].x));
        pB[1] = __uint_as_float(f2tf32(pb[i].y));
        pB[2] = __uint_as_float(f2tf32(pb[i].z));
        pB[3] = __uint_as_float(f2tf32(pb[i].w));
    }
    __syncthreads();

    for (int ic = 0; ic < NCHUNK; ic++) {
        // prefetch next chunk into registers
        if (ic + 1 < NCHUNK) {
            const float* An = A + (ic + 1) * BKc;
            const float* Bn = B + (ic + 1) * BKc;
            #pragma unroll
            for (int i = 0; i < 4; i++) {
                int u = tid + i * 256;
                int r = u >> 3, c4 = u & 7;
                pa[i] = *(const float4*)(An + (size_t)(m0 + r) * GK + c4 * 4);
                pb[i] = *(const float4*)(Bn + (size_t)(n0 + r) * GK + c4 * 4);
            }
        }

        const float* Ab = As + (ic & 1) * BUF_F;
        const float* Bb = Bs + (ic & 1) * BUF_F;
        #pragma unroll
        for (int ks = 0; ks < 4; ks++) {
            int kb = ks * 8;
            uint32_t af[2][4];
            #pragma unroll
            for (int mt = 0; mt < 2; mt++) {
                int r = wm * 32 + mt * 16 + grp;
                af[mt][0] = __float_as_uint(Ab[r * PADs + kb + qd]);
                af[mt][1] = __float_as_uint(Ab[(r + 8) * PADs + kb + qd]);
                af[mt][2] = __float_as_uint(Ab[r * PADs + kb + qd + 4]);
                af[mt][3] = __float_as_uint(Ab[(r + 8) * PADs + kb + qd + 4]);
            }
            #pragma unroll
            for (int nt = 0; nt < 8; nt++) {
                int c = wn * 64 + nt * 8 + grp;
                uint32_t b0 = __float_as_uint(Bb[c * PADs + kb + qd]);
                uint32_t b1 = __float_as_uint(Bb[c * PADs + kb + qd + 4]);
                mma16n8k8(acc[0][nt], af[0], b0, b1);
                mma16n8k8(acc[1][nt], af[1], b0, b1);
            }
        }

        if (ic + 1 < NCHUNK) {
            float* Ad = As + ((ic + 1) & 1) * BUF_F;
            float* Bd = Bs + ((ic + 1) & 1) * BUF_F;
            #pragma unroll
            for (int i = 0; i < 4; i++) {
                int u = tid + i * 256;
                int r = u >> 3, c4 = u & 7;
                float* pA = Ad + r * PADs + c4 * 4;
                pA[0] = __uint_as_float(f2tf32(pa[i].x));
                pA[1] = __uint_as_float(f2tf32(pa[i].y));
                pA[2] = __uint_as_float(f2tf32(pa[i].z));
                pA[3] = __uint_as_float(f2tf32(pa[i].w));
                float* pB = Bd + r * PADs + c4 * 4;
                pB[0] = __uint_as_float(f2tf32(pb[i].x));
                pB[1] = __uint_as_float(f2tf32(pb[i].y));
                pB[2] = __uint_as_float(f2tf32(pb[i].z));
                pB[3] = __uint_as_float(f2tf32(pb[i].w));
            }
            __syncthreads();
        }
    }

    // epilogue: direct float2 stores
    #pragma unroll
    for (int mt = 0; mt < 2; mt++) {
        #pragma unroll
        for (int nt = 0; nt < 8; nt++) {
            int r = m0 + wm * 32 + mt * 16 + grp;
            int c = n0 + wn * 64 + nt * 8 + qd * 2;
            *(float2*)(C + (size_t)r * N + c) =
                make_float2(acc[mt][nt][0], acc[mt][nt][1]);
            *(float2*)(C + (size_t)(r + 8) * N + c) =
                make_float2(acc[mt][nt][2], acc[mt][nt][3]);
        }
    }
}

// ---------------- block reduction helper (256 threads) ----------------
__device__ __forceinline__ void block_reduce4(float& a, float& b, float& c, float& d) {
    #pragma unroll
    for (int o = 16; o; o >>= 1) {
        a += __shfl_xor_sync(0xffffffffu, a, o);
        b += __shfl_xor_sync(0xffffffffu, b, o);
        c += __shfl_xor_sync(0xffffffffu, c, o);
        d += __shfl_xor_sync(0xffffffffu, d, o);
    }
    __shared__ float s[4][8];
    int w = threadIdx.x >> 5, lane = threadIdx.x & 31;
    if (lane == 0) { s[0][w] = a; s[1][w] = b; s[2][w] = c; s[3][w] = d; }
    __syncthreads();
    a = b = c = d = 0.f;
    #pragma unroll
    for (int i = 0; i < 8; i++) { a += s[0][i]; b += s[1][i]; c += s[2][i]; d += s[3][i]; }
    __syncthreads();
}

// ---------------- kernel 1: LN1 ----------------
__global__ void ln1_kernel(const float* __restrict__ x,
                           const float* __restrict__ w,
                           const float* __restrict__ bia) {
    int t = blockIdx.x;
    int tid = threadIdx.x;
    const float4* xr = (const float4*)(x + (size_t)t * DD);
    float4 v = xr[tid];
    float s  = v.x + v.y + v.z + v.w;
    float ss = v.x*v.x + v.y*v.y + v.z*v.z + v.w*v.w;
    float z0 = 0.f, z1 = 0.f;
    block_reduce4(s, ss, z0, z1);
    float mu  = s * (1.0f / DD);
    float var = ss * (1.0f / DD) - mu * mu;
    float inv = rsqrtf(var + EPS);
    float4 wv = ((const float4*)w)[tid];
    float4 bv = ((const float4*)bia)[tid];
    float4 o;
    o.x = (v.x - mu) * inv * wv.x + bv.x;
    o.y = (v.y - mu) * inv * wv.y + bv.y;
    o.z = (v.z - mu) * inv * wv.z + bv.z;
    o.w = (v.w - mu) * inv * wv.w + bv.w;
    ((float4*)(g_h + (size_t)t * DD))[tid] = o;
}

// ---------------- kernel 3: QK LayerNorm + RoPE + transpose ----------------
__global__ void qk_rope_kernel(const float* __restrict__ qw,
                               const float* __restrict__ kw) {
    int t = blockIdx.x;
    int b = t >> 11;
    int l = t & 2047;
    int tid = threadIdx.x;
    const float4* row = (const float4*)(g_qkv + (size_t)t * 3 * DD);
    float4 q = row[tid];
    float4 k = row[256 + tid];
    float4 v = row[512 + tid];

    float qs  = q.x + q.y + q.z + q.w;
    float qss = q.x*q.x + q.y*q.y + q.z*q.z + q.w*q.w;
    float ks  = k.x + k.y + k.z + k.w;
    float kss = k.x*k.x + k.y*k.y + k.z*k.z + k.w*k.w;
    block_reduce4(qs, qss, ks, kss);
    float muq = qs * (1.0f / DD);
    float vq  = qss * (1.0f / DD) - muq * muq;
    float iq  = rsqrtf(vq + EPS);
    float muk = ks * (1.0f / DD);
    float vk  = kss * (1.0f / DD) - muk * muk;
    float ik  = rsqrtf(vk + EPS);

    __shared__ float qn[DD];
    __shared__ float kn[DD];
    float4 qwv = ((const float4*)qw)[tid];
    float4 kwv = ((const float4*)kw)[tid];
    int d0 = tid * 4;
    qn[d0+0] = (q.x - muq) * iq * qwv.x;
    qn[d0+1] = (q.y - muq) * iq * qwv.y;
    qn[d0+2] = (q.z - muq) * iq * qwv.z;
    qn[d0+3] = (q.w - muq) * iq * qwv.w;
    kn[d0+0] = (k.x - muk) * ik * kwv.x;
    kn[d0+1] = (k.y - muk) * ik * kwv.y;
    kn[d0+2] = (k.z - muk) * ik * kwv.z;
    kn[d0+3] = (k.w - muk) * ik * kwv.w;
    __syncthreads();

    int h   = d0 >> 6;
    int dh0 = d0 & 63;
    float oq[4], ok[4];
    #pragma unroll
    for (int j = 0; j < 4; j++) {
        int dh = dh0 + j;
        int fi = dh & 31;
        float invf = powf(10000.0f, -((float)(2 * fi)) / 64.0f);
        float ang  = (float)l * invf;
        float c = cosf(ang), s = sinf(ang);
        float qv = qn[d0 + j];
        float kv = kn[d0 + j];
        float qp = (dh < 32) ? -qn[d0 + j + 32] : qn[d0 + j - 32];
        float kp = (dh < 32) ? -kn[d0 + j + 32] : kn[d0 + j - 32];
        oq[j] = qv * c + qp * s;
        ok[j] = kv * c + kp * s;
    }
    size_t oidx = (((size_t)(b * HH + h) * LL + l) * DHH + dh0);
    *(float4*)(g_q + oidx) = make_float4(oq[0], oq[1], oq[2], oq[3]);
    *(float4*)(g_k + oidx) = make_float4(ok[0], ok[1], ok[2], ok[3]);
    *(float4*)(g_v + oidx) = v;
}

// ---------------- kernel 4: flash-style masked attention ----------------
// seq_id is SORTED along L per batch row => a 64-token tile's segment range is
// [seq[first], seq[last]]. Fully non-overlapping (q,k) tile pairs are exact
// no-ops in the online softmax (p=0, scl=1) and are skipped before any load.
__global__ void attn_kernel(const int* __restrict__ seq_id) {
    extern __shared__ float smf[];
    float* Qs  = smf;
    float* KPs = smf + 64 * 65;
    float* Vs  = KPs + 64 * 65;
    __shared__ int kseq[64];

    int qt = blockIdx.x;
    int bh = blockIdx.y;
    int b  = bh >> 4;
    int hh = bh & 15;
    int tid = threadIdx.x;
    int tx = tid & 15, ty = tid >> 4;

    const int qmin = seq_id[b * LL + qt * 64];
    const int qmax = seq_id[b * LL + qt * 64 + 63];

    const float* Qg = g_q + ((size_t)bh * LL + qt * 64) * DHH;
    #pragma unroll
    for (int i = 0; i < 4; i++) {
        int idx = tid + i * 256;
        int m = idx >> 4;
        int d4 = (idx & 15) * 4;
        float4 qv = *(const float4*)(Qg + m * DHH + d4);
        Qs[(d4+0)*65 + m] = qv.x;
        Qs[(d4+1)*65 + m] = qv.y;
        Qs[(d4+2)*65 + m] = qv.z;
        Qs[(d4+3)*65 + m] = qv.w;
    }
    int qseq[4];
    #pragma unroll
    for (int i = 0; i < 4; i++)
        qseq[i] = seq_id[b * LL + qt * 64 + ty * 4 + i];

    float m_i[4], l_i[4], O[4][4];
    #pragma unroll
    for (int i = 0; i < 4; i++) {
        m_i[i] = -1e30f; l_i[i] = 0.f;
        #pragma unroll
        for (int j = 0; j < 4; j++) O[i][j] = 0.f;
    }

    for (int kt = 0; kt < LL / 64; kt++) {
        // tile-skip: block-uniform, exact no-op tiles (sorted seq_id)
        int kmin = seq_id[b * LL + kt * 64];
        int kmax = seq_id[b * LL + kt * 64 + 63];
        if (kmax < qmin || kmin > qmax) continue;

        __syncthreads();
        const float* Kg = g_k + ((size_t)bh * LL + kt * 64) * DHH;
        const float* Vg = g_v + ((size_t)bh * LL + kt * 64) * DHH;
        #pragma unroll
        for (int i = 0; i < 4; i++) {
            int idx = tid + i * 256;
            int n = idx >> 4;
            int d4 = (idx & 15) * 4;
            float4 kv = *(const float4*)(Kg + n * DHH + d4);
            KPs[(d4+0)*65 + n] = kv.x;
            KPs[(d4+1)*65 + n] = kv.y;
            KPs[(d4+2)*65 + n] = kv.z;
            KPs[(d4+3)*65 + n] = kv.w;
            float4 vv = *(const float4*)(Vg + n * DHH + d4);
            *(float4*)&Vs[n * 64 + d4] = vv;
        }
        if (tid < 64) kseq[tid] = seq_id[b * LL + kt * 64 + tid];
        __syncthreads();

        float S[4][4];
        #pragma unroll
        for (int i = 0; i < 4; i++)
            #pragma unroll
            for (int j = 0; j < 4; j++) S[i][j] = 0.f;
        for (int kk = 0; kk < 64; kk++) {
            float a0 = Qs[kk*65 + ty*4 + 0];
            float a1 = Qs[kk*65 + ty*4 + 1];
            float a2 = Qs[kk*65 + ty*4 + 2];
            float a3 = Qs[kk*65 + ty*4 + 3];
            float b0 = KPs[kk*65 + tx*4 + 0];
            float b1 = KPs[kk*65 + tx*4 + 1];
            float b2 = KPs[kk*65 + tx*4 + 2];
            float b3 = KPs[kk*65 + tx*4 + 3];
            S[0][0] = fmaf(a0,b0,S[0][0]); S[0][1] = fmaf(a0,b1,S[0][1]);
            S[0][2] = fmaf(a0,b2,S[0][2]); S[0][3] = fmaf(a0,b3,S[0][3]);
            S[1][0] = fmaf(a1,b0,S[1][0]); S[1][1] = fmaf(a1,b1,S[1][1]);
            S[1][2] = fmaf(a1,b2,S[1][2]); S[1][3] = fmaf(a1,b3,S[1][3]);
            S[2][0] = fmaf(a2,b0,S[2][0]); S[2][1] = fmaf(a2,b1,S[2][1]);
            S[2][2] = fmaf(a2,b2,S[2][2]); S[2][3] = fmaf(a2,b3,S[2][3]);
            S[3][0] = fmaf(a3,b0,S[3][0]); S[3][1] = fmaf(a3,b1,S[3][1]);
            S[3][2] = fmaf(a3,b2,S[3][2]); S[3][3] = fmaf(a3,b3,S[3][3]);
        }

        int kse[4];
        #pragma unroll
        for (int j = 0; j < 4; j++) kse[j] = kseq[tx * 4 + j];
        #pragma unroll
        for (int i = 0; i < 4; i++)
            #pragma unroll
            for (int j = 0; j < 4; j++)
                S[i][j] = (qseq[i] == kse[j]) ? S[i][j] * 0.125f : -1e30f;

        float scl[4];
        #pragma unroll
        for (int i = 0; i < 4; i++) {
            float rmax = fmaxf(fmaxf(S[i][0], S[i][1]), fmaxf(S[i][2], S[i][3]));
            #pragma unroll
            for (int o = 8; o; o >>= 1)
                rmax = fmaxf(rmax, __shfl_xor_sync(0xffffffffu, rmax, o));
            float mn = fmaxf(m_i[i], rmax);
            scl[i] = expf(m_i[i] - mn);
            m_i[i] = mn;
            float rsum = 0.f;
            #pragma unroll
            for (int j = 0; j < 4; j++) {
                float p = expf(S[i][j] - mn);
                S[i][j] = p;
                rsum += p;
            }
            #pragma unroll
            for (int o = 8; o; o >>= 1)
                rsum += __shfl_xor_sync(0xffffffffu, rsum, o);
            l_i[i] = l_i[i] * scl[i] + rsum;
            #pragma unroll
            for (int j = 0; j < 4; j++) O[i][j] *= scl[i];
        }

        __syncthreads();
        #pragma unroll
        for (int i = 0; i < 4; i++)
            #pragma unroll
            for (int j = 0; j < 4; j++)
                KPs[(tx*4 + j)*65 + ty*4 + i] = S[i][j];
        __syncthreads();

        for (int nn = 0; nn < 64; nn++) {
            float a0 = KPs[nn*65 + ty*4 + 0];
            float a1 = KPs[nn*65 + ty*4 + 1];
            float a2 = KPs[nn*65 + ty*4 + 2];
            float a3 = KPs[nn*65 + ty*4 + 3];
            float4 bv = *(const float4*)&Vs[nn*64 + tx*4];
            O[0][0] = fmaf(a0,bv.x,O[0][0]); O[0][1] = fmaf(a0,bv.y,O[0][1]);
            O[0][2] = fmaf(a0,bv.z,O[0][2]); O[0][3] = fmaf(a0,bv.w,O[0][3]);
            O[1][0] = fmaf(a1,bv.x,O[1][0]); O[1][1] = fmaf(a1,bv.y,O[1][1]);
            O[1][2] = fmaf(a1,bv.z,O[1][2]); O[1][3] = fmaf(a1,bv.w,O[1][3]);
            O[2][0] = fmaf(a2,bv.x,O[2][0]); O[2][1] = fmaf(a2,bv.y,O[2][1]);
            O[2][2] = fmaf(a2,bv.z,O[2][2]); O[2][3] = fmaf(a2,bv.w,O[2][3]);
            O[3][0] = fmaf(a3,bv.x,O[3][0]); O[3][1] = fmaf(a3,bv.y,O[3][1]);
            O[3][2] = fmaf(a3,bv.z,O[3][2]); O[3][3] = fmaf(a3,bv.w,O[3][3]);
        }
    }

    #pragma unroll
    for (int i = 0; i < 4; i++) {
        float inv = 1.0f / l_i[i];
        int t = b * LL + qt * 64 + ty * 4 + i;
        float4 o = make_float4(O[i][0]*inv, O[i][1]*inv, O[i][2]*inv, O[i][3]*inv);
        *(float4*)(g_ctx + (size_t)t * DD + hh * DHH + tx * 4) = o;
    }
}

// ---------------- launch ----------------
extern "C" void kernel_launch(void* const* d_in, const int* in_sizes, int n_in,
                              void* d_out, int out_size) {
    const float* x     = (const float*)d_in[0];
    const int*   seq   = (const int*)  d_in[1];
    const float* ln1w  = (const float*)d_in[2];
    const float* ln1b  = (const float*)d_in[3];
    const float* wqkv  = (const float*)d_in[4];
    const float* qlnw  = (const float*)d_in[5];
    const float* klnw  = (const float*)d_in[6];
    const float* outw  = (const float*)d_in[7];
    float* out = (float*)d_out;

    void *ph, *pqkv, *pctx;
    cudaGetSymbolAddress(&ph, g_h);
    cudaGetSymbolAddress(&pqkv, g_qkv);
    cudaGetSymbolAddress(&pctx, g_ctx);

    cudaFuncSetAttribute(gemm_mma_tf32, cudaFuncAttributeMaxDynamicSharedMemorySize, GEMM_SMEM);

    // 1) LN1
    ln1_kernel<<<TT, 256>>>(x, ln1w, ln1b);

    // 2) QKV GEMM: [4096,3072] = h x wqkv^T  (tf32 mma.sync)
    gemm_mma_tf32<<<dim3(3 * DD / 128, TT / 128), 256, GEMM_SMEM>>>(
        (const float*)ph, wqkv, (float*)pqkv, 3 * DD);

    // 3) QK LN + RoPE + transpose
    qk_rope_kernel<<<TT, 256>>>(qlnw, klnw);

    // 4) attention (mask-aware tile skipping)
    const int attn_smem = (64 * 65 + 64 * 65 + 64 * 64) * (int)sizeof(float);
    cudaFuncSetAttribute(attn_kernel, cudaFuncAttributeMaxDynamicSharedMemorySize, attn_smem);
    attn_kernel<<<dim3(LL / 64, BB * HH), 256, attn_smem>>>(seq);

    // 5) output projection: [4096,1024] = ctx x out_w^T  (tf32 mma.sync)
    gemm_mma_tf32<<<dim3(DD / 128, TT / 128), 256, GEMM_SMEM>>>(
        (const float*)pctx, outw, out, DD);
}

// round 5
// speedup vs baseline: 4.6524x; 1.2557x over previous
#include <cuda_runtime.h>
#include <cuda_bf16.h>
#include <cstdint>
#include <math.h>

// Problem constants
#define BB 2
#define LL 2048
#define DD 1024
#define HH 16
#define DHH 64
#define TT (BB*LL)          // 4096 tokens
#define EPS 1e-5f

// -------- scratch (device globals: allocation-free rule) --------
__device__ float g_h[TT * DD];            // LN1 output
__device__ float g_qkv[TT * 3 * DD];      // QKV GEMM output
__device__ float g_q[TT * DD];            // [B,H,L,DH] roped q
__device__ float g_k[TT * DD];            // [B,H,L,DH] roped k
__device__ float g_v[TT * DD];            // [B,H,L,DH] v
__device__ float g_ctx[TT * DD];          // attention output

__device__ __forceinline__ uint32_t f2tf32(float f) {
    uint32_t r; asm("cvt.rna.tf32.f32 %0, %1;" : "=r"(r) : "f"(f)); return r;
}

__device__ __forceinline__ void mma16n8k8(float* d, const uint32_t* a,
                                          uint32_t b0, uint32_t b1) {
    asm volatile(
        "mma.sync.aligned.m16n8k8.row.col.f32.tf32.tf32.f32 "
        "{%0,%1,%2,%3}, {%4,%5,%6,%7}, {%8,%9}, {%0,%1,%2,%3};"
        : "+f"(d[0]), "+f"(d[1]), "+f"(d[2]), "+f"(d[3])
        : "r"(a[0]), "r"(a[1]), "r"(a[2]), "r"(a[3]), "r"(b0), "r"(b1));
}

// bf16 helpers for attention MMA
__device__ __forceinline__ uint32_t bfpack(float a, float b) {
    __nv_bfloat162 t = __floats2bfloat162_rn(a, b);
    return *reinterpret_cast<uint32_t*>(&t);
}
__device__ __forceinline__ void bfsplit(float a, float b, uint32_t& hi, uint32_t& lo) {
    __nv_bfloat16 ha = __float2bfloat16_rn(a), hb = __float2bfloat16_rn(b);
    float ra = a - __bfloat162float(ha);
    float rb = b - __bfloat162float(hb);
    __nv_bfloat162 h; h.x = ha; h.y = hb;
    hi = *reinterpret_cast<uint32_t*>(&h);
    lo = bfpack(ra, rb);
}
__device__ __forceinline__ void mma16816(float* c, uint32_t a0, uint32_t a1,
                                         uint32_t a2, uint32_t a3,
                                         uint32_t b0, uint32_t b1) {
    asm volatile(
        "mma.sync.aligned.m16n8k16.row.col.f32.bf16.bf16.f32 "
        "{%0,%1,%2,%3}, {%4,%5,%6,%7}, {%8,%9}, {%0,%1,%2,%3};"
        : "+f"(c[0]), "+f"(c[1]), "+f"(c[2]), "+f"(c[3])
        : "r"(a0), "r"(a1), "r"(a2), "r"(a3), "r"(b0), "r"(b1));
}

// ===================== tf32 mma.sync GEMM =====================
// C[M,N] = A[M,1024] * B[N,1024]^T. Tile 128x128, BK=32, 8 warps (32x64 each).
#define GK 1024
#define BKc 32
#define NCHUNK (GK / BKc)    // 32
#define PADs 36
#define BUF_F (128 * PADs)   // floats per (matrix, buffer)
#define GEMM_SMEM (4 * BUF_F * 4)   // 2 bufs x (A+B) = 73728 B

__global__ __launch_bounds__(256)
void gemm_mma_tf32(const float* __restrict__ A, const float* __restrict__ B,
                   float* __restrict__ C, int N) {
    extern __shared__ float sm[];
    float* As = sm;                 // [2][128][PADs]
    float* Bs = sm + 2 * BUF_F;     // [2][128][PADs]

    const int tid = threadIdx.x;
    const int wid = tid >> 5, lane = tid & 31;
    const int grp = lane >> 2, qd = lane & 3;
    const int wm = wid >> 1, wn = wid & 1;   // 4 m-warps x 2 n-warps
    const int m0 = blockIdx.y * 128;
    const int n0 = blockIdx.x * 128;

    float acc[2][8][4];
    #pragma unroll
    for (int i = 0; i < 2; i++)
        #pragma unroll
        for (int j = 0; j < 8; j++)
            #pragma unroll
            for (int q = 0; q < 4; q++) acc[i][j][q] = 0.f;

    float4 pa[4], pb[4];
    // load chunk 0
    #pragma unroll
    for (int i = 0; i < 4; i++) {
        int u = tid + i * 256;
        int r = u >> 3, c4 = u & 7;
        pa[i] = *(const float4*)(A + (size_t)(m0 + r) * GK + c4 * 4);
        pb[i] = *(const float4*)(B + (size_t)(n0 + r) * GK + c4 * 4);
    }
    #pragma unroll
    for (int i = 0; i < 4; i++) {
        int u = tid + i * 256;
        int r = u >> 3, c4 = u & 7;
        float* pA = As + r * PADs + c4 * 4;
        pA[0] = __uint_as_float(f2tf32(pa[i].x));
        pA[1] = __uint_as_float(f2tf32(pa[i].y));
        pA[2] = __uint_as_float(f2tf32(pa[i].z));
        pA[3] = __uint_as_float(f2tf32(pa[i].w));
        float* pB = Bs + r * PADs + c4 * 4;
        pB[0] = __uint_as_float(f2tf32(pb[i].x));
        pB[1] = __uint_as_float(f2tf32(pb[i].y));
        pB[2] = __uint_as_float(f2tf32(pb[i].z));
        pB[3] = __uint_as_float(f2tf32(pb[i].w));
    }
    __syncthreads();

    for (int ic = 0; ic < NCHUNK; ic++) {
        // prefetch next chunk into registers
        if (ic + 1 < NCHUNK) {
            const float* An = A + (ic + 1) * BKc;
            const float* Bn = B + (ic + 1) * BKc;
            #pragma unroll
            for (int i = 0; i < 4; i++) {
                int u = tid + i * 256;
                int r = u >> 3, c4 = u & 7;
                pa[i] = *(const float4*)(An + (size_t)(m0 + r) * GK + c4 * 4);
                pb[i] = *(const float4*)(Bn + (size_t)(n0 + r) * GK + c4 * 4);
            }
        }

        const float* Ab = As + (ic & 1) * BUF_F;
        const float* Bb = Bs + (ic & 1) * BUF_F;
        #pragma unroll
        for (int ks = 0; ks < 4; ks++) {
            int kb = ks * 8;
            uint32_t af[2][4];
            #pragma unroll
            for (int mt = 0; mt < 2; mt++) {
                int r = wm * 32 + mt * 16 + grp;
                af[mt][0] = __float_as_uint(Ab[r * PADs + kb + qd]);
                af[mt][1] = __float_as_uint(Ab[(r + 8) * PADs + kb + qd]);
                af[mt][2] = __float_as_uint(Ab[r * PADs + kb + qd + 4]);
                af[mt][3] = __float_as_uint(Ab[(r + 8) * PADs + kb + qd + 4]);
            }
            #pragma unroll
            for (int nt = 0; nt < 8; nt++) {
                int c = wn * 64 + nt * 8 + grp;
                uint32_t b0 = __float_as_uint(Bb[c * PADs + kb + qd]);
                uint32_t b1 = __float_as_uint(Bb[c * PADs + kb + qd + 4]);
                mma16n8k8(acc[0][nt], af[0], b0, b1);
                mma16n8k8(acc[1][nt], af[1], b0, b1);
            }
        }

        if (ic + 1 < NCHUNK) {
            float* Ad = As + ((ic + 1) & 1) * BUF_F;
            float* Bd = Bs + ((ic + 1) & 1) * BUF_F;
            #pragma unroll
            for (int i = 0; i < 4; i++) {
                int u = tid + i * 256;
                int r = u >> 3, c4 = u & 7;
                float* pA = Ad + r * PADs + c4 * 4;
                pA[0] = __uint_as_float(f2tf32(pa[i].x));
                pA[1] = __uint_as_float(f2tf32(pa[i].y));
                pA[2] = __uint_as_float(f2tf32(pa[i].z));
                pA[3] = __uint_as_float(f2tf32(pa[i].w));
                float* pB = Bd + r * PADs + c4 * 4;
                pB[0] = __uint_as_float(f2tf32(pb[i].x));
                pB[1] = __uint_as_float(f2tf32(pb[i].y));
                pB[2] = __uint_as_float(f2tf32(pb[i].z));
                pB[3] = __uint_as_float(f2tf32(pb[i].w));
            }
            __syncthreads();
        }
    }

    // epilogue: direct float2 stores
    #pragma unroll
    for (int mt = 0; mt < 2; mt++) {
        #pragma unroll
        for (int nt = 0; nt < 8; nt++) {
            int r = m0 + wm * 32 + mt * 16 + grp;
            int c = n0 + wn * 64 + nt * 8 + qd * 2;
            *(float2*)(C + (size_t)r * N + c) =
                make_float2(acc[mt][nt][0], acc[mt][nt][1]);
            *(float2*)(C + (size_t)(r + 8) * N + c) =
                make_float2(acc[mt][nt][2], acc[mt][nt][3]);
        }
    }
}

// ---------------- block reduction helper (256 threads) ----------------
__device__ __forceinline__ void block_reduce4(float& a, float& b, float& c, float& d) {
    #pragma unroll
    for (int o = 16; o; o >>= 1) {
        a += __shfl_xor_sync(0xffffffffu, a, o);
        b += __shfl_xor_sync(0xffffffffu, b, o);
        c += __shfl_xor_sync(0xffffffffu, c, o);
        d += __shfl_xor_sync(0xffffffffu, d, o);
    }
    __shared__ float s[4][8];
    int w = threadIdx.x >> 5, lane = threadIdx.x & 31;
    if (lane == 0) { s[0][w] = a; s[1][w] = b; s[2][w] = c; s[3][w] = d; }
    __syncthreads();
    a = b = c = d = 0.f;
    #pragma unroll
    for (int i = 0; i < 8; i++) { a += s[0][i]; b += s[1][i]; c += s[2][i]; d += s[3][i]; }
    __syncthreads();
}

// ---------------- kernel 1: LN1 ----------------
__global__ void ln1_kernel(const float* __restrict__ x,
                           const float* __restrict__ w,
                           const float* __restrict__ bia) {
    int t = blockIdx.x;
    int tid = threadIdx.x;
    const float4* xr = (const float4*)(x + (size_t)t * DD);
    float4 v = xr[tid];
    float s  = v.x + v.y + v.z + v.w;
    float ss = v.x*v.x + v.y*v.y + v.z*v.z + v.w*v.w;
    float z0 = 0.f, z1 = 0.f;
    block_reduce4(s, ss, z0, z1);
    float mu  = s * (1.0f / DD);
    float var = ss * (1.0f / DD) - mu * mu;
    float inv = rsqrtf(var + EPS);
    float4 wv = ((const float4*)w)[tid];
    float4 bv = ((const float4*)bia)[tid];
    float4 o;
    o.x = (v.x - mu) * inv * wv.x + bv.x;
    o.y = (v.y - mu) * inv * wv.y + bv.y;
    o.z = (v.z - mu) * inv * wv.z + bv.z;
    o.w = (v.w - mu) * inv * wv.w + bv.w;
    ((float4*)(g_h + (size_t)t * DD))[tid] = o;
}

// ---------------- kernel 3: QK LayerNorm + RoPE + transpose ----------------
__global__ void qk_rope_kernel(const float* __restrict__ qw,
                               const float* __restrict__ kw) {
    int t = blockIdx.x;
    int b = t >> 11;
    int l = t & 2047;
    int tid = threadIdx.x;
    const float4* row = (const float4*)(g_qkv + (size_t)t * 3 * DD);
    float4 q = row[tid];
    float4 k = row[256 + tid];
    float4 v = row[512 + tid];

    float qs  = q.x + q.y + q.z + q.w;
    float qss = q.x*q.x + q.y*q.y + q.z*q.z + q.w*q.w;
    float ks  = k.x + k.y + k.z + k.w;
    float kss = k.x*k.x + k.y*k.y + k.z*k.z + k.w*k.w;
    block_reduce4(qs, qss, ks, kss);
    float muq = qs * (1.0f / DD);
    float vq  = qss * (1.0f / DD) - muq * muq;
    float iq  = rsqrtf(vq + EPS);
    float muk = ks * (1.0f / DD);
    float vk  = kss * (1.0f / DD) - muk * muk;
    float ik  = rsqrtf(vk + EPS);

    __shared__ float qn[DD];
    __shared__ float kn[DD];
    float4 qwv = ((const float4*)qw)[tid];
    float4 kwv = ((const float4*)kw)[tid];
    int d0 = tid * 4;
    qn[d0+0] = (q.x - muq) * iq * qwv.x;
    qn[d0+1] = (q.y - muq) * iq * qwv.y;
    qn[d0+2] = (q.z - muq) * iq * qwv.z;
    qn[d0+3] = (q.w - muq) * iq * qwv.w;
    kn[d0+0] = (k.x - muk) * ik * kwv.x;
    kn[d0+1] = (k.y - muk) * ik * kwv.y;
    kn[d0+2] = (k.z - muk) * ik * kwv.z;
    kn[d0+3] = (k.w - muk) * ik * kwv.w;
    __syncthreads();

    int h   = d0 >> 6;
    int dh0 = d0 & 63;
    float oq[4], ok[4];
    #pragma unroll
    for (int j = 0; j < 4; j++) {
        int dh = dh0 + j;
        int fi = dh & 31;
        float invf = powf(10000.0f, -((float)(2 * fi)) / 64.0f);
        float ang  = (float)l * invf;
        float c = cosf(ang), s = sinf(ang);
        float qv = qn[d0 + j];
        float kv = kn[d0 + j];
        float qp = (dh < 32) ? -qn[d0 + j + 32] : qn[d0 + j - 32];
        float kp = (dh < 32) ? -kn[d0 + j + 32] : kn[d0 + j - 32];
        oq[j] = qv * c + qp * s;
        ok[j] = kv * c + kp * s;
    }
    size_t oidx = (((size_t)(b * HH + h) * LL + l) * DHH + dh0);
    *(float4*)(g_q + oidx) = make_float4(oq[0], oq[1], oq[2], oq[3]);
    *(float4*)(g_k + oidx) = make_float4(ok[0], ok[1], ok[2], ok[3]);
    *(float4*)(g_v + oidx) = v;
}

// ---------------- kernel 4: flash attention, bf16-split3 mma.sync ----------------
// 128 threads = 4 warps; warp w owns rows [16w, 16w+16) of the 64-row Q tile and
// computes full 64-col strips of S and O, so softmax reductions stay inside the
// 4-thread qd group. K buffer is reused for P. Split x = hi + lo (bf16) and
// compute hi*hi + hi*lo + lo*hi => ~fp32 accuracy at 1.5x a single tf32 MMA cost.
#define AW 36   // 32 data words + 4 pad (stride % 32 == 4 -> conflict-free frags)
#define ATTN_SMEM (6 * 64 * AW * 4)   // 55296 B

__global__ __launch_bounds__(128)
void attn_kernel(const int* __restrict__ seq_id) {
    extern __shared__ uint32_t smw[];
    uint32_t* Qh  = smw;                // [64][AW] bf16x2 (k-pairs)
    uint32_t* Ql  = Qh  + 64 * AW;
    uint32_t* KPh = Ql  + 64 * AW;      // K (then P) hi
    uint32_t* KPl = KPh + 64 * AW;
    uint32_t* VTh = KPl + 64 * AW;      // V^T: [d][n-pairs]
    uint32_t* VTl = VTh + 64 * AW;
    __shared__ int kseq[64];

    const int qt = blockIdx.x, bh = blockIdx.y;
    const int b = bh >> 4, hh = bh & 15;
    const int tid = threadIdx.x;
    const int w = tid >> 5, lane = tid & 31;
    const int grp = lane >> 2, qd = lane & 3;

    const int qbase = b * LL + qt * 64;
    const int qmin = seq_id[qbase];
    const int qmax = seq_id[qbase + 63];

    // stage Q (scale 1/8 folded in exactly; split into bf16 hi/lo planes)
    {
        const float4* Qg = (const float4*)(g_q + ((size_t)bh * LL + qt * 64) * DHH);
        #pragma unroll
        for (int i = 0; i < 8; i++) {
            int idx = tid + i * 128;
            int r = idx >> 4, c4 = idx & 15;
            float4 qv = Qg[r * 16 + c4];
            qv.x *= 0.125f; qv.y *= 0.125f; qv.z *= 0.125f; qv.w *= 0.125f;
            uint32_t h0, l0, h1, l1;
            bfsplit(qv.x, qv.y, h0, l0);
            bfsplit(qv.z, qv.w, h1, l1);
            Qh[r * AW + c4 * 2]     = h0;  Qh[r * AW + c4 * 2 + 1] = h1;
            Ql[r * AW + c4 * 2]     = l0;  Ql[r * AW + c4 * 2 + 1] = l1;
        }
    }
    const int row0 = w * 16 + grp, row1 = row0 + 8;
    const int qs0 = seq_id[qbase + row0];
    const int qs1 = seq_id[qbase + row1];

    float m0 = -1e30f, m1 = -1e30f, l0s = 0.f, l1s = 0.f;
    float O[8][4];
    #pragma unroll
    for (int dt = 0; dt < 8; dt++)
        #pragma unroll
        for (int q = 0; q < 4; q++) O[dt][q] = 0.f;

    for (int kt = 0; kt < LL / 64; kt++) {
        const int kb = b * LL + kt * 64;
        if (seq_id[kb + 63] < qmin || seq_id[kb] > qmax) continue;  // exact no-op tile

        __syncthreads();   // prior-iteration smem reads complete
        // stage K
        {
            const float4* Kg = (const float4*)(g_k + ((size_t)bh * LL + kt * 64) * DHH);
            #pragma unroll
            for (int i = 0; i < 8; i++) {
                int idx = tid + i * 128;
                int r = idx >> 4, c4 = idx & 15;
                float4 kv = Kg[r * 16 + c4];
                uint32_t h0, l0, h1, l1;
                bfsplit(kv.x, kv.y, h0, l0);
                bfsplit(kv.z, kv.w, h1, l1);
                KPh[r * AW + c4 * 2]     = h0;  KPh[r * AW + c4 * 2 + 1] = h1;
                KPl[r * AW + c4 * 2]     = l0;  KPl[r * AW + c4 * 2 + 1] = l1;
            }
        }
        // stage V transposed: VT[d][n-pair]
        {
            const float* Vg = g_v + ((size_t)bh * LL + kt * 64) * DHH;
            #pragma unroll
            for (int i = 0; i < 4; i++) {
                int idx = tid + i * 128;
                int p = idx & 31, c4 = idx >> 5;     // n-pair p, d-group c4 (0..15)
                float4 v0 = *(const float4*)(Vg + (2 * p) * DHH + c4 * 4);
                float4 v1 = *(const float4*)(Vg + (2 * p + 1) * DHH + c4 * 4);
                const float a0[4] = {v0.x, v0.y, v0.z, v0.w};
                const float a1[4] = {v1.x, v1.y, v1.z, v1.w};
                #pragma unroll
                for (int j = 0; j < 4; j++) {
                    uint32_t h, l;
                    bfsplit(a0[j], a1[j], h, l);
                    VTh[(c4 * 4 + j) * AW + p] = h;
                    VTl[(c4 * 4 + j) * AW + p] = l;
                }
            }
        }
        if (tid < 64) kseq[tid] = seq_id[kb + tid];
        __syncthreads();

        // ---- S = Q K^T (3-term split) ----
        float S[8][4];
        #pragma unroll
        for (int nt = 0; nt < 8; nt++)
            #pragma unroll
            for (int q = 0; q < 4; q++) S[nt][q] = 0.f;
        #pragma unroll
        for (int ks = 0; ks < 4; ks++) {
            int r0w = (w * 16 + grp) * AW, r1w = (w * 16 + grp + 8) * AW;
            int kw0 = ks * 8 + qd;
            uint32_t ah0 = Qh[r0w + kw0],     ah1 = Qh[r1w + kw0];
            uint32_t ah2 = Qh[r0w + kw0 + 4], ah3 = Qh[r1w + kw0 + 4];
            uint32_t al0 = Ql[r0w + kw0],     al1 = Ql[r1w + kw0];
            uint32_t al2 = Ql[r0w + kw0 + 4], al3 = Ql[r1w + kw0 + 4];
            #pragma unroll
            for (int nt = 0; nt < 8; nt++) {
                int nw = (nt * 8 + grp) * AW;
                uint32_t bh0 = KPh[nw + kw0], bh1 = KPh[nw + kw0 + 4];
                uint32_t bl0 = KPl[nw + kw0], bl1 = KPl[nw + kw0 + 4];
                mma16816(S[nt], ah0, ah1, ah2, ah3, bh0, bh1);
                mma16816(S[nt], ah0, ah1, ah2, ah3, bl0, bl1);
                mma16816(S[nt], al0, al1, al2, al3, bh0, bh1);
            }
        }

        // ---- mask ----
        #pragma unroll
        for (int nt = 0; nt < 8; nt++) {
            int c0 = kseq[nt * 8 + 2 * qd];
            int c1 = kseq[nt * 8 + 2 * qd + 1];
            if (c0 != qs0) S[nt][0] = -1e30f;
            if (c1 != qs0) S[nt][1] = -1e30f;
            if (c0 != qs1) S[nt][2] = -1e30f;
            if (c1 != qs1) S[nt][3] = -1e30f;
        }

        // ---- online softmax (row reductions within qd group) ----
        float mx0 = -1e30f, mx1 = -1e30f;
        #pragma unroll
        for (int nt = 0; nt < 8; nt++) {
            mx0 = fmaxf(mx0, fmaxf(S[nt][0], S[nt][1]));
            mx1 = fmaxf(mx1, fmaxf(S[nt][2], S[nt][3]));
        }
        mx0 = fmaxf(mx0, __shfl_xor_sync(0xffffffffu, mx0, 1));
        mx0 = fmaxf(mx0, __shfl_xor_sync(0xffffffffu, mx0, 2));
        mx1 = fmaxf(mx1, __shfl_xor_sync(0xffffffffu, mx1, 1));
        mx1 = fmaxf(mx1, __shfl_xor_sync(0xffffffffu, mx1, 2));
        float mn0 = fmaxf(m0, mx0), mn1 = fmaxf(m1, mx1);
        float sc0 = __expf(m0 - mn0), sc1 = __expf(m1 - mn1);
        m0 = mn0; m1 = mn1;
        float s0 = 0.f, s1 = 0.f;
        #pragma unroll
        for (int nt = 0; nt < 8; nt++) {
            S[nt][0] = __expf(S[nt][0] - mn0);
            S[nt][1] = __expf(S[nt][1] - mn0);
            S[nt][2] = __expf(S[nt][2] - mn1);
            S[nt][3] = __expf(S[nt][3] - mn1);
            s0 += S[nt][0] + S[nt][1];
            s1 += S[nt][2] + S[nt][3];
        }
        s0 += __shfl_xor_sync(0xffffffffu, s0, 1);
        s0 += __shfl_xor_sync(0xffffffffu, s0, 2);
        s1 += __shfl_xor_sync(0xffffffffu, s1, 1);
        s1 += __shfl_xor_sync(0xffffffffu, s1, 2);
        l0s = l0s * sc0 + s0;
        l1s = l1s * sc1 + s1;
        #pragma unroll
        for (int dt = 0; dt < 8; dt++) {
            O[dt][0] *= sc0; O[dt][1] *= sc0;
            O[dt][2] *= sc1; O[dt][3] *= sc1;
        }

        __syncthreads();   // all K fragment reads done before P overwrite
        // ---- write P (split) into KP buffers as [m][n-pair] ----
        #pragma unroll
        for (int nt = 0; nt < 8; nt++) {
            uint32_t h, l;
            bfsplit(S[nt][0], S[nt][1], h, l);
            KPh[(w * 16 + grp) * AW + nt * 4 + qd] = h;
            KPl[(w * 16 + grp) * AW + nt * 4 + qd] = l;
            bfsplit(S[nt][2], S[nt][3], h, l);
            KPh[(w * 16 + grp + 8) * AW + nt * 4 + qd] = h;
            KPl[(w * 16 + grp + 8) * AW + nt * 4 + qd] = l;
        }
        __syncthreads();

        // ---- O += P V (3-term split, K-dim = n) ----
        #pragma unroll
        for (int ks = 0; ks < 4; ks++) {
            int r0w = (w * 16 + grp) * AW, r1w = (w * 16 + grp + 8) * AW;
            int kw0 = ks * 8 + qd;
            uint32_t ah0 = KPh[r0w + kw0],     ah1 = KPh[r1w + kw0];
            uint32_t ah2 = KPh[r0w + kw0 + 4], ah3 = KPh[r1w + kw0 + 4];
            uint32_t al0 = KPl[r0w + kw0],     al1 = KPl[r1w + kw0];
            uint32_t al2 = KPl[r0w + kw0 + 4], al3 = KPl[r1w + kw0 + 4];
            #pragma unroll
            for (int dt = 0; dt < 8; dt++) {
                int dw = (dt * 8 + grp) * AW;
                uint32_t bh0 = VTh[dw + kw0], bh1 = VTh[dw + kw0 + 4];
                uint32_t bl0 = VTl[dw + kw0], bl1 = VTl[dw + kw0 + 4];
                mma16816(O[dt], ah0, ah1, ah2, ah3, bh0, bh1);
                mma16816(O[dt], ah0, ah1, ah2, ah3, bl0, bl1);
                mma16816(O[dt], al0, al1, al2, al3, bh0, bh1);
            }
        }
    }

    // epilogue
    float inv0 = 1.0f / l0s, inv1 = 1.0f / l1s;
    const int t0 = b * LL + qt * 64 + row0;
    const int t1 = b * LL + qt * 64 + row1;
    #pragma unroll
    for (int dt = 0; dt < 8; dt++) {
        int c = hh * DHH + dt * 8 + 2 * qd;
        *(float2*)(g_ctx + (size_t)t0 * DD + c) =
            make_float2(O[dt][0] * inv0, O[dt][1] * inv0);
        *(float2*)(g_ctx + (size_t)t1 * DD + c) =
            make_float2(O[dt][2] * inv1, O[dt][3] * inv1);
    }
}

// ---------------- launch ----------------
extern "C" void kernel_launch(void* const* d_in, const int* in_sizes, int n_in,
                              void* d_out, int out_size) {
    const float* x     = (const float*)d_in[0];
    const int*   seq   = (const int*)  d_in[1];
    const float* ln1w  = (const float*)d_in[2];
    const float* ln1b  = (const float*)d_in[3];
    const float* wqkv  = (const float*)d_in[4];
    const float* qlnw  = (const float*)d_in[5];
    const float* klnw  = (const float*)d_in[6];
    const float* outw  = (const float*)d_in[7];
    float* out = (float*)d_out;

    void *ph, *pqkv, *pctx;
    cudaGetSymbolAddress(&ph, g_h);
    cudaGetSymbolAddress(&pqkv, g_qkv);
    cudaGetSymbolAddress(&pctx, g_ctx);

    cudaFuncSetAttribute(gemm_mma_tf32, cudaFuncAttributeMaxDynamicSharedMemorySize, GEMM_SMEM);
    cudaFuncSetAttribute(attn_kernel, cudaFuncAttributeMaxDynamicSharedMemorySize, ATTN_SMEM);

    // 1) LN1
    ln1_kernel<<<TT, 256>>>(x, ln1w, ln1b);

    // 2) QKV GEMM: [4096,3072] = h x wqkv^T  (tf32 mma.sync)
    gemm_mma_tf32<<<dim3(3 * DD / 128, TT / 128), 256, GEMM_SMEM>>>(
        (const float*)ph, wqkv, (float*)pqkv, 3 * DD);

    // 3) QK LN + RoPE + transpose
    qk_rope_kernel<<<TT, 256>>>(qlnw, klnw);

    // 4) attention (tile-skip + bf16-split3 mma)
    attn_kernel<<<dim3(LL / 64, BB * HH), 128, ATTN_SMEM>>>(seq);

    // 5) output projection: [4096,1024] = ctx x out_w^T  (tf32 mma.sync)
    gemm_mma_tf32<<<dim3(DD / 128, TT / 128), 256, GEMM_SMEM>>>(
        (const float*)pctx, outw, out, DD);
}